// round 17
// baseline (speedup 1.0000x reference)
#include <cuda_runtime.h>
#include <math.h>
#include <stdint.h>

#define NB   32
#define CC   256
#define C4   64
#define LL   6
#define TT   64
#define VV   25
#define EPS  1e-5f
#define SLOPE 0.2f
#define NPAIR 45
#define TPS  (CC * LL)                    // tmax tiles per sample = 1536

// scratch (no cudaMalloc allowed)
__device__ float g_xt[NB * CC * LL * VV];     // [n][c][l][v]
__device__ float g_gate[NB * CC * LL];        // [n][c][l]
__device__ int   g_cnt[NB];                   // per-sample completion counters
                                              // (self-resetting -> replay-safe)

__constant__ int c_pv[NPAIR] = {
    1,0,20,
    0,20,12,16,2,4,8,
    12,16,2,4,8,13,17,3,5,9,
    13,17,3,5,9,14,18,6,10,
    14,18,6,10,15,19,7,11,
    15,19,7,11,21,22,23,24};
__constant__ int c_off[LL + 1] = {0,3,10,20,29,37,45};
__constant__ float c_inv_cnt[LL] = {1.f/3.f, 1.f/7.f, 1.f/10.f, 1.f/9.f, 1.f/8.f, 1.f/8.f};

// dynamic smem overlay (floats): tile (1600) reused by the middle phase
#define SMX_X     0                        // shX  [10][128] = 1280
#define SMX_PARTS 1280                     // parts[2][10][64] = 1280
#define SMX_S     2560                     // sh_s [64][6] = 384
#define SMX_E     2944                     // sh_e [64][6] = 384
#define SMX_G     3328                     // sh_G [36]
#define SMX_IDX   3364                     // sh_idx [18] ints
#define DSM_FLOATS 3392
#define DSM_BYTES  (DSM_FLOATS * 4)        // 13568 B -> 16 blocks/SM ok

__device__ __forceinline__ void cp_async4(void* dst_smem, const void* src) {
    uint32_t d = (uint32_t)__cvta_generic_to_shared(dst_smem);
    asm volatile("cp.async.ca.shared.global [%0], [%1], 4;\n" :: "r"(d), "l"(src));
}
__device__ __forceinline__ void cp_wait_all_f() {
    asm volatile("cp.async.wait_all;\n" ::: "memory");
}

// ---------------------------------------------------------------------------
// Kernel 1: T-max (one block per (n,c,l) tile) + last-block-per-sample does
// the whole middle inline (threadfence-reduction pattern: no spinning).
// ---------------------------------------------------------------------------
__global__ __launch_bounds__(128, 16) void k_tmax_mid(
    const float* __restrict__ x,
    const float* __restrict__ W_down, const float* __restrict__ b_down,
    const float* __restrict__ g_down, const float* __restrict__ be_down,
    const float* __restrict__ m_down, const float* __restrict__ v_down,
    const float* __restrict__ W_edge, const float* __restrict__ g_edge,
    const float* __restrict__ be_edge, const float* __restrict__ m_edge,
    const float* __restrict__ v_edge, const float* __restrict__ W_agg,
    const float* __restrict__ b_agg) {
    extern __shared__ float sm[];
    __shared__ int is_last;
    const int b = blockIdx.x;                 // (n*C + c)*L + l
    const int tid = threadIdx.x;
    const int n = b / TPS;

    // ---- T-max for this tile ----
    {
        float4* tile4 = reinterpret_cast<float4*>(sm);
        float* tile = sm;
        const float4* xb = reinterpret_cast<const float4*>(x) + (size_t)b * 400;
        #pragma unroll
        for (int i = 0; i < 3; i++) tile4[tid + i * 128] = xb[tid + i * 128];
        if (tid < 16) tile4[tid + 384] = xb[tid + 384];
        __syncthreads();
        if (tid < VV) {
            float m = tile[tid];
            #pragma unroll
            for (int t = 1; t < TT; t++) m = fmaxf(m, tile[t * VV + tid]);
            g_xt[(size_t)b * VV + tid] = m;
        }
    }

    // ---- completion count; last block of this sample does the middle ----
    __syncthreads();
    if (tid == 0) {
        __threadfence();                      // publish g_xt stores
        const int prev = atomicAdd(&g_cnt[n], 1);
        is_last = (prev == TPS - 1);
        if (is_last) g_cnt[n] = 0;            // reset for next replay
    }
    __syncthreads();
    if (!is_last) return;
    __threadfence();                          // acquire peers' g_xt stores

    // ================= middle for sample n (128 threads) =================
    float* shX   = sm + SMX_X;                // [p][128] one c-half
    float* parts = sm + SMX_PARTS;            // [g][p][o]
    float* sh_s  = sm + SMX_S;                // [c][l]
    float* sh_e  = sm + SMX_E;                // [o][l]
    float* sh_G  = sm + SMX_G;
    int*   sh_idx = reinterpret_cast<int*>(sm + SMX_IDX);
    const int o = tid & 63;
    const int g = tid >> 6;                   // 0/1

    // Stage 1: s[o][l] via two 128-channel passes per layer
    for (int l = 0; l < LL; l++) {
        const int p0 = c_off[l];
        const int cnt = c_off[l + 1] - p0;
        for (int h = 0; h < 2; h++) {
            __syncthreads();                  // shX free
            const float* xb = g_xt + ((size_t)(n * CC + h * 128 + tid) * LL + l) * VV;
            for (int p = 0; p < cnt; p++)
                cp_async4(&shX[p * 128 + tid], xb + c_pv[p0 + p]);
            cp_wait_all_f();
            __syncthreads();
            const float4* wr = reinterpret_cast<const float4*>(
                W_down + o * CC + h * 128 + g * 64);
            for (int p = 0; p < cnt; p++) {
                const float4* xp = reinterpret_cast<const float4*>(
                    shX + p * 128 + g * 64);
                float a = 0.f;
                #pragma unroll
                for (int i = 0; i < 16; i++) {
                    const float4 w = wr[i];   // L1-resident after p=0
                    const float4 xv = xp[i];
                    a += w.x * xv.x + w.y * xv.y + w.z * xv.z + w.w * xv.w;
                }
                float* slot = &parts[(g * 10 + p) * 64 + o];
                if (h == 0) *slot = a; else *slot += a;
            }
        }
        __syncthreads();
        if (tid < 64) {
            const float gs  = g_down[tid] * rsqrtf(v_down[tid] + EPS);
            const float shb = be_down[tid] - m_down[tid] * gs;
            const float bd  = b_down[tid];
            float ssum = 0.f;
            for (int p = 0; p < cnt; p++) {
                const float y = (parts[p * 64 + tid] + parts[640 + p * 64 + tid]
                                 + bd) * gs + shb;
                ssum += fmaxf(y, 0.f);
            }
            sh_s[tid * LL + l] = ssum * c_inv_cnt[l];
        }
    }
    __syncthreads();

    // Stage 2a: Gram matrix
    if (tid < LL * LL) {
        const int i = tid / LL, j = tid % LL;
        float acc = 0.f;
        #pragma unroll 8
        for (int c = 0; c < C4; c++) acc += sh_s[c * LL + i] * sh_s[c * LL + j];
        sh_G[tid] = acc;
    }
    __syncthreads();

    // Stage 2b: top-3 neighbors (stable tie-break matching lax.top_k)
    if (tid < LL) {
        float d[LL];
        bool used[LL];
        const float sqi = sh_G[tid * LL + tid];
        #pragma unroll
        for (int j = 0; j < LL; j++) {
            d[j] = 2.f * sh_G[tid * LL + j] - sqi - sh_G[j * LL + j];
            used[j] = false;
        }
        #pragma unroll
        for (int k = 0; k < 3; k++) {
            float best = -INFINITY; int bi = 0;
            #pragma unroll
            for (int j = 0; j < LL; j++)
                if (!used[j] && d[j] > best) { best = d[j]; bi = j; }
            used[bi] = true;
            sh_idx[tid * 3 + k] = bi;
        }
    }
    __syncthreads();

    // Stage 2c: EdgeConv + BN + leaky + max over k (W_edge via L2 float4)
    for (int item = tid; item < LL * C4; item += 128) {
        const int oo = item & 63;
        const int l  = item >> 6;
        const float4* w14 = reinterpret_cast<const float4*>(W_edge + oo * 128);
        const int n0 = sh_idx[l * 3], n1 = sh_idx[l * 3 + 1], n2 = sh_idx[l * 3 + 2];
        float base = 0.f, a0 = 0.f, a1 = 0.f, a2 = 0.f;
        #pragma unroll 4
        for (int i = 0; i < 16; i++) {
            const float4 w = w14[i];
            const float4 w2 = w14[16 + i];
            const int c = 4 * i;
            #pragma unroll
            for (int q = 0; q < 4; q++) {
                const float wq = (&w.x)[q];
                base += ((&w2.x)[q] - wq) * sh_s[(c + q) * LL + l];
                a0 += wq * sh_s[(c + q) * LL + n0];
                a1 += wq * sh_s[(c + q) * LL + n1];
                a2 += wq * sh_s[(c + q) * LL + n2];
            }
        }
        const float gs  = g_edge[oo] * rsqrtf(v_edge[oo] + EPS);
        const float shb = be_edge[oo] - m_edge[oo] * gs;
        float m = -INFINITY;
        float ys[3] = {a0 + base, a1 + base, a2 + base};
        #pragma unroll
        for (int k = 0; k < 3; k++) {
            float y = ys[k] * gs + shb;
            y = fmaxf(y, 0.f) + SLOPE * fminf(y, 0.f);
            m = fmaxf(m, y);
        }
        sh_e[oo * LL + l] = m;
    }
    __syncthreads();

    // Stage 2d: att = W_agg @ e + b_agg ; gate = sigmoid (2 rows per thread)
    #pragma unroll
    for (int r = 0; r < 2; r++) {
        const int oc = tid + r * 128;
        float a[LL];
        const float bb = b_agg[oc];
        #pragma unroll
        for (int l = 0; l < LL; l++) a[l] = bb;
        const float4* wr = reinterpret_cast<const float4*>(W_agg + oc * C4);
        #pragma unroll 4
        for (int i = 0; i < 16; i++) {
            const float4 w = wr[i];
            const int c = 4 * i;
            #pragma unroll
            for (int l = 0; l < LL; l++)
                a[l] += w.x * sh_e[c * LL + l] + w.y * sh_e[(c+1) * LL + l]
                      + w.z * sh_e[(c+2) * LL + l] + w.w * sh_e[(c+3) * LL + l];
        }
        float* gp = g_gate + ((size_t)n * CC + oc) * LL;
        #pragma unroll
        for (int l = 0; l < LL; l++)
            gp[l] = 1.f / (1.f + expf(-a[l]));
    }
}

// ---------------------------------------------------------------------------
// Kernel 2 (measured 53.2us @ 84.3% DRAM): out = sum_l x * gate   (float4)
// ---------------------------------------------------------------------------
__global__ __launch_bounds__(256) void k_gatesum(const float* __restrict__ x,
                                                 float* __restrict__ out) {
    const int gid = blockIdx.x * 256 + threadIdx.x;     // [0, 32*256*400)
    const int tv4 = gid % 400;
    const int nc  = gid / 400;
    const float4* xb = reinterpret_cast<const float4*>(x) + (size_t)nc * (LL * 400) + tv4;
    const float* gp = g_gate + (size_t)nc * LL;
    float4 acc = make_float4(0.f, 0.f, 0.f, 0.f);
    #pragma unroll
    for (int l = 0; l < LL; l++) {
        const float g = gp[l];
        const float4 xv = xb[l * 400];
        acc.x += xv.x * g; acc.y += xv.y * g;
        acc.z += xv.z * g; acc.w += xv.w * g;
    }
    reinterpret_cast<float4*>(out)[(size_t)nc * 400 + tv4] = acc;
}

// ---------------------------------------------------------------------------
extern "C" void kernel_launch(void* const* d_in, const int* in_sizes, int n_in,
                              void* d_out, int out_size) {
    const float* x       = (const float*)d_in[0];
    const float* W_down  = (const float*)d_in[1];
    const float* b_down  = (const float*)d_in[2];
    const float* g_down  = (const float*)d_in[3];
    const float* be_down = (const float*)d_in[4];
    const float* m_down  = (const float*)d_in[5];
    const float* v_down  = (const float*)d_in[6];
    const float* W_edge  = (const float*)d_in[7];
    const float* g_edge  = (const float*)d_in[8];
    const float* be_edge = (const float*)d_in[9];
    const float* m_edge  = (const float*)d_in[10];
    const float* v_edge  = (const float*)d_in[11];
    const float* W_agg   = (const float*)d_in[12];
    const float* b_agg   = (const float*)d_in[13];
    float* out = (float*)d_out;

    k_tmax_mid<<<NB * CC * LL, 128, DSM_BYTES>>>(
        x, W_down, b_down, g_down, be_down, m_down, v_down,
        W_edge, g_edge, be_edge, m_edge, v_edge, W_agg, b_agg);
    k_gatesum<<<(NB * CC * 400) / 256, 256>>>(x, out);
}